// round 9
// baseline (speedup 1.0000x reference)
#include <cuda_runtime.h>
#include <cstdint>

// Problem: B=8, C=256, H=W=64, K=3, pad=1, stride=1
// out_flat[f] = keyflat[f] * qv[f/9], f in [0, 9*4096) per (b,c) slice
//   keyflat[f] = zero-padded key at (l>>6 + kk/3 - 1, (l&63) + kk%3 - 1)
//   qv[l']     = zero-padded query at fq = 9*l'+4 (same patch formula)
// CTA = (slice bc, quarter q): l in [q*1024, q*1024+1024), all 9 kk.
// f = f0 + 4096*kk, 4096 = 9*455+1:
//   lp0(kk) = a0 + 455*kk + cr,  cr = [r0+kk >= 9],  rem = r0+kk - 9*cr
//   window base(kk) = b0 + 455*kk  (b0 = q*1024/9)  ->  idx = kk*QW + (a0-b0) + cr
#define HW   64
#define KP   68                 // key tile pitch (1 left halo + 64 + 3 right pad)
#define KR   18                 // image rows q*16-1 .. q*16+16
#define QW   116                // qv window entries per kk (d0<=113, +cr, +1 for .y)
#define QVT  (9 * QW)           // 1044
#define LSZ  4096

__device__ __forceinline__ float qpatch(const float* __restrict__ qb, int lp) {
    // qv[lp] = zero-padded query at fq = 9*lp + 4
    float v = 0.0f;
    if ((unsigned)lp < (unsigned)LSZ) {
        const int fq  = 9 * lp + 4;
        const int kkq = fq >> 12;
        const int lq  = fq & 4095;
        const int row = (lq >> 6) + kkq / 3 - 1;
        const int col = (lq & 63) + kkq % 3 - 1;
        if (((unsigned)row < (unsigned)HW) & ((unsigned)col < (unsigned)HW))
            v = __ldg(qb + row * HW + col);
    }
    return v;
}

__global__ void __launch_bounds__(256, 8)
appearance_kernel(const float* __restrict__ key,
                  const float* __restrict__ query,
                  float* __restrict__ out) {
    __shared__ alignas(16) float  ktile[KR * KP];  // 4896 B
    __shared__ alignas(16) float2 qvp[QVT];        // 8352 B: {qv[lp], qv[lp+1]}

    const int tid = threadIdx.x;
    const int bid = blockIdx.x;        // 0..8191
    const int bc  = bid >> 2;          // slice 0..2047
    const int q   = bid & 3;           // quarter 0..3
    const int q1024 = q << 10;

    const float*  kb  = key   + (size_t)bc * LSZ;
    const float4* kb4 = (const float4*)kb;
    const float*  qb  = query + (size_t)bc * LSZ;

    // ---- zero halo columns (cols 0, 65, 66, 67 of all 18 rows) ----
    if (tid < KR * 4) {
        const int lr = tid >> 2, hc = tid & 3;
        ktile[lr * KP + (hc == 0 ? 0 : 64 + hc)] = 0.0f;
    }

    // ---- key tile: local row lr = image row (q*16 - 1 + lr) ----
    #pragma unroll
    for (int k = 0; k < 2; k++) {
        const int i = tid + k * 256;               // need 288 of 512
        if (i < KR * 16) {
            const int lr = i >> 4, c4 = i & 15;
            const int ir = q * 16 - 1 + lr;
            float4 v = make_float4(0.f, 0.f, 0.f, 0.f);
            if ((unsigned)ir < (unsigned)HW) v = kb4[ir * 16 + c4];
            float* p = &ktile[lr * KP + 1 + c4 * 4];
            p[0] = v.x; p[1] = v.y; p[2] = v.z; p[3] = v.w;
        }
    }

    // ---- qv pair windows: qvp[kk*QW+jj] = {qv[b0+455kk+jj], qv[b0+455kk+jj+1]} ----
    const unsigned b0 = (unsigned)q1024 / 9u;      // once per thread (uniform)
    #pragma unroll
    for (int k = 0; k < 5; k++) {
        const int j = tid + k * 256;               // need 1044 of 1280
        if (j < QVT) {
            const int kk = (unsigned)j / QW;
            const int jj = j - kk * QW;
            const int lp = (int)b0 + 455 * kk + jj;    // pure add: no division
            qvp[j] = make_float2(qpatch(qb, lp), qpatch(qb, lp + 1));
        }
    }
    __syncthreads();

    // ---- per-thread division ONCE; loop is adds/compares only ----
    const int f0 = q1024 + (tid << 2);
    const unsigned a0 = (unsigned)f0 / 9u;         // one mul-hi div
    const int r0 = f0 - (int)a0 * 9;               // 0..8
    const int d0 = (int)(a0 - b0);                 // 0..113

    float4* out4 = (float4*)out + (size_t)bc * 9216 + q * 256 + tid;
    const int lrow = tid >> 4;                     // 0..15
    const int col  = (tid & 15) << 2;              // 0..60, 16B aligned

    #pragma unroll
    for (int dr = 0; dr < 3; dr++) {
        const float* wp = &ktile[(lrow + dr) * KP + col];
        const float4 a = *(const float4*)wp;       // w0..w3
        const float2 b = *(const float2*)(wp + 4); // w4,w5
        const float w0 = a.x, w1 = a.y, w2 = a.z, w3 = a.w, w4 = b.x, w5 = b.y;

        #pragma unroll
        for (int dc = 0; dc < 3; dc++) {
            const int kk  = 3 * dr + dc;
            const int rk  = r0 + kk;               // 0..16
            const int cr  = (rk >= 9) ? 1 : 0;
            const int rem = rk - (cr ? 9 : 0);     // 0..8
            const float2 qq = qvp[kk * QW + d0 + cr];   // one LDS.64
            const float q0 = qq.x, qn = qq.y;

            float4 o;
            o.x = (dc == 0 ? w0 : dc == 1 ? w1 : w2) * q0;
            o.y = (dc == 0 ? w1 : dc == 1 ? w2 : w3) * (rem >= 8 ? qn : q0);
            o.z = (dc == 0 ? w2 : dc == 1 ? w3 : w4) * (rem >= 7 ? qn : q0);
            o.w = (dc == 0 ? w3 : dc == 1 ? w4 : w5) * (rem >= 6 ? qn : q0);
            __stcs(&out4[kk * 1024], o);           // streaming store
        }
    }
}

extern "C" void kernel_launch(void* const* d_in, const int* in_sizes, int n_in,
                              void* d_out, int out_size) {
    const float* key   = (const float*)d_in[0];
    const float* query = (const float*)d_in[1];
    float* out = (float*)d_out;

    appearance_kernel<<<8192, 256>>>(key, query, out);
}

// round 10
// speedup vs baseline: 1.0305x; 1.0305x over previous
#include <cuda_runtime.h>
#include <cstdint>

// Problem: B=8, C=256, H=W=64, K=3, pad=1, stride=1
// out_flat[f] = keyflat[f] * qv[f/9], f in [0, 9*4096) per (b,c) slice
//   keyflat[f] = zero-padded key at (l>>6 + kk/3 - 1, (l&63) + kk%3 - 1)
//   qv[l']     = zero-padded query at fq = 9*l'+4 (same patch formula)
// CTA = (slice bc, quarter q): l in [q*1024, q*1024+1024), all 9 kk.
// f = f0 + 4096*kk, 4096 = 9*455+1:
//   lp0(kk) = a0 + 455*kk + cr,  cr = [r0+kk >= 9],  rem = r0+kk - 9*cr
//   window base(kk) = b0 + 455*kk exactly (b0 = q*1024/9, no correction term)
//   idx into window kk: (kk<<7) + (a0-b0) + cr      (QW = 128, d0 <= 113)
#define HW   64
#define KP   68                 // key tile pitch (1 left halo + 64 + 3 right pad)
#define KR   18                 // image rows q*16-1 .. q*16+16
#define QW   128                // qv window stride (power of 2; 116 used)
#define QVT  (9 * QW)           // 1152
#define LSZ  4096

__device__ __forceinline__ float qpatch(const float* __restrict__ qb, int lp) {
    // qv[lp] = zero-padded query at fq = 9*lp + 4
    float v = 0.0f;
    if ((unsigned)lp < (unsigned)LSZ) {
        const int fq  = 9 * lp + 4;
        const int kkq = fq >> 12;
        const int lq  = fq & 4095;
        const int row = (lq >> 6) + kkq / 3 - 1;
        const int col = (lq & 63) + kkq % 3 - 1;
        if (((unsigned)row < (unsigned)HW) & ((unsigned)col < (unsigned)HW))
            v = __ldg(qb + row * HW + col);
    }
    return v;
}

__global__ void __launch_bounds__(256, 8)
appearance_kernel(const float* __restrict__ key,
                  const float* __restrict__ query,
                  float* __restrict__ out) {
    __shared__ alignas(16) float ktile[KR * KP];   // 4896 B
    __shared__ alignas(16) float qvs[QVT];         // 4608 B

    const int tid = threadIdx.x;
    const int bid = blockIdx.x;        // 0..8191
    const int bc  = bid >> 2;          // slice 0..2047
    const int q   = bid & 3;           // quarter 0..3
    const int q1024 = q << 10;

    const float*  kb  = key   + (size_t)bc * LSZ;
    const float4* kb4 = (const float4*)kb;
    const float*  qb  = query + (size_t)bc * LSZ;

    // ---- zero halo columns (cols 0, 65, 66, 67 of all 18 rows) ----
    if (tid < KR * 4) {
        const int lr = tid >> 2, hc = tid & 3;
        ktile[lr * KP + (hc == 0 ? 0 : 64 + hc)] = 0.0f;
    }

    // ---- key tile: local row lr = image row (q*16 - 1 + lr) ----
    #pragma unroll
    for (int k = 0; k < 2; k++) {
        const int i = tid + k * 256;               // need 288 of 512
        if (i < KR * 16) {
            const int lr = i >> 4, c4 = i & 15;
            const int ir = q * 16 - 1 + lr;
            float4 v = make_float4(0.f, 0.f, 0.f, 0.f);
            if ((unsigned)ir < (unsigned)HW) v = kb4[ir * 16 + c4];
            float* p = &ktile[lr * KP + 1 + c4 * 4];
            p[0] = v.x; p[1] = v.y; p[2] = v.z; p[3] = v.w;
        }
    }

    // ---- qv windows: qvs[(kk<<7)+jj] = qv[b0 + 455*kk + jj]; pure-add fill ----
    const unsigned b0 = (unsigned)q1024 / 9u;      // uniform per CTA
    #pragma unroll
    for (int k = 0; k < 5; k++) {
        const int j = tid + k * 256;               // need 1152 of 1280
        if (j < QVT) {
            const int kk = j >> 7;                 // shift, no div
            const int jj = j & 127;
            const int lp = (int)b0 + 455 * kk + jj;
            qvs[j] = qpatch(qb, lp);               // bounds-checked (lp may be 4096)
        }
    }
    __syncthreads();

    // ---- per-thread division ONCE; loop is adds/compares only ----
    const int f0 = q1024 + (tid << 2);
    const unsigned a0 = (unsigned)f0 / 9u;         // one mul-hi div
    const int r0 = f0 - (int)a0 * 9;               // 0..8
    const int d0 = (int)(a0 - b0);                 // 0..113

    float4* out4 = (float4*)out + (size_t)bc * 9216 + q * 256 + tid;
    const int lrow = tid >> 4;                     // 0..15
    const int col  = (tid & 15) << 2;              // 0..60, 16B aligned

    #pragma unroll
    for (int dr = 0; dr < 3; dr++) {
        const float* wp = &ktile[(lrow + dr) * KP + col];
        const float4 a = *(const float4*)wp;       // w0..w3
        const float2 b = *(const float2*)(wp + 4); // w4,w5
        const float w0 = a.x, w1 = a.y, w2 = a.z, w3 = a.w, w4 = b.x, w5 = b.y;

        #pragma unroll
        for (int dc = 0; dc < 3; dc++) {
            const int kk  = 3 * dr + dc;
            const int rk  = r0 + kk;               // 0..16
            const int cr  = (rk >= 9) ? 1 : 0;
            const int rem = rk - (cr ? 9 : 0);     // 0..8
            const int idx = (kk << 7) + d0 + cr;
            const float q0 = qvs[idx];
            const float qn = qvs[idx + 1];

            float4 o;
            o.x = (dc == 0 ? w0 : dc == 1 ? w1 : w2) * q0;
            o.y = (dc == 0 ? w1 : dc == 1 ? w2 : w3) * (rem >= 8 ? qn : q0);
            o.z = (dc == 0 ? w2 : dc == 1 ? w3 : w4) * (rem >= 7 ? qn : q0);
            o.w = (dc == 0 ? w3 : dc == 1 ? w4 : w5) * (rem >= 6 ? qn : q0);
            __stcs(&out4[kk * 1024], o);           // streaming store
        }
    }
}

extern "C" void kernel_launch(void* const* d_in, const int* in_sizes, int n_in,
                              void* d_out, int out_size) {
    const float* key   = (const float*)d_in[0];
    const float* query = (const float*)d_in[1];
    float* out = (float*)d_out;

    appearance_kernel<<<8192, 256>>>(key, query, out);
}